// round 17
// baseline (speedup 1.0000x reference)
#include <cuda_runtime.h>
#include <cuda_fp16.h>
#include <cstdint>

// ---------------------------------------------------------------------------
// RegionAttention R17:
//  - attention: 3 CTAs/SM (launch_bounds(256,3)); reg pressure cut by
//    reloading Q frags per tile (no persistent aQ) and packing P to fp16
//    during the softmax pass (S fp32 regs die early).
//  - q stored fp16 from QKV epilogue (g_q16): halves q gmem traffic.
//  - GEMM / prepass: unchanged from R16.
// ---------------------------------------------------------------------------

#define LTOK   16384
#define DIMC   512
#define QKVC   1536
#define NH     8
#define HD     64
#define NREG   1024
#define SCALE_Q 0.125f
#define LOG2E  1.4426950408889634f

__device__ __half g_q16[LTOK * DIMC];      // q fp16, bias applied
__device__ __half g_kv[LTOK * 1024];       // [tok][head][k|v][64] fp16
__device__ __half g_att[LTOK * DIMC];      // attention output fp16, token order
__device__ __half g_x16[LTOK * DIMC];      // x converted
__device__ __half g_w1[QKVC * DIMC];       // qkv_w converted
__device__ __half g_w2[DIMC * DIMC];       // proj_w converted

__device__ __forceinline__ int tok_index(int rg, int n) {
    return ((rg >> 2) << 12) | ((n >> 5) << 7) | ((rg & 3) << 5) | (n & 31);
}

__device__ __forceinline__ uint32_t smem_u32(const void* p) {
    uint32_t a;
    asm("{ .reg .u64 t; cvta.to.shared.u64 t, %1; cvt.u32.u64 %0, t; }"
        : "=r"(a) : "l"(p));
    return a;
}

__device__ __forceinline__ float ex2f(float x) {
    float y;
    asm("ex2.approx.ftz.f32 %0, %1;" : "=f"(y) : "f"(x));
    return y;
}

__device__ __forceinline__ void mma_h(float c[4],
                                      uint32_t a0, uint32_t a1,
                                      uint32_t a2, uint32_t a3,
                                      uint32_t b0, uint32_t b1) {
    asm volatile(
        "mma.sync.aligned.m16n8k16.row.col.f32.f16.f16.f32 "
        "{%0,%1,%2,%3}, {%4,%5,%6,%7}, {%8,%9}, {%0,%1,%2,%3};"
        : "+f"(c[0]), "+f"(c[1]), "+f"(c[2]), "+f"(c[3])
        : "r"(a0), "r"(a1), "r"(a2), "r"(a3), "r"(b0), "r"(b1));
}

__device__ __forceinline__ uint32_t h2pack(float x, float y) {
    __half2 h = __floats2half2_rn(x, y);
    return *(uint32_t*)&h;
}

#define LDM_X4(r0_, r1_, r2_, r3_, addr) \
    asm volatile("ldmatrix.sync.aligned.m8n8.x4.shared.b16 {%0,%1,%2,%3}, [%4];" \
        : "=r"(r0_), "=r"(r1_), "=r"(r2_), "=r"(r3_) : "r"(addr))
#define LDM_X4_T(r0_, r1_, r2_, r3_, addr) \
    asm volatile("ldmatrix.sync.aligned.m8n8.x4.trans.shared.b16 {%0,%1,%2,%3}, [%4];" \
        : "=r"(r0_), "=r"(r1_), "=r"(r2_), "=r"(r3_) : "r"(addr))

#define CP_ASYNC16(dst, src) \
    asm volatile("cp.async.cg.shared.global [%0], [%1], 16;" \
                 :: "r"(dst), "l"(src) : "memory")
#define CP_COMMIT() asm volatile("cp.async.commit_group;" ::: "memory")
#define CP_WAIT0()  asm volatile("cp.async.wait_group 0;" ::: "memory")

// ===========================================================================
// Prepass: fp32 -> fp16 convert (vectorized, grid-stride).
// ===========================================================================
__global__ __launch_bounds__(256) void cvt16_kernel(
    const float* __restrict__ src, __half* __restrict__ dst, int n4)
{
    int i = blockIdx.x * 256 + threadIdx.x;
    int stride = gridDim.x * 256;
    for (; i < n4; i += stride) {
        float4 v = *(const float4*)(src + i * 4);
        uint2 o;
        o.x = h2pack(v.x, v.y);
        o.y = h2pack(v.z, v.w);
        *(uint2*)(dst + i * 4) = o;
    }
}

// ===========================================================================
// fp16 GEMM, one-sync cp.async pipeline: C = A @ W^T + bias.
// Tile 128x128, K-chunk 64, 256 threads = 8 warps (2m x 4n). 2 CTAs/SM.
// QKV mode (Q16 != nullptr): cols [0,512) -> fp16 Q16, [512,1536) -> KV.
// Proj mode (Q16 == nullptr): fp32 C (stride N).
// ===========================================================================
#define GSTRIDE 72
#define GOFF_W  (128 * GSTRIDE)
#define GBUFH   (2 * 128 * GSTRIDE)               // fp16 elems per buffer
#define GEMM_SMEM_BYTES (2 * GBUFH * 2)           // 73728

__device__ __forceinline__ void gemm_issue_chunk(
    uint32_t sbu, int bufoff, const __half* __restrict__ A,
    const __half* __restrict__ W, int m0, int n0, int K, int k0, int tid)
{
#pragma unroll
    for (int s = 0; s < 4; s++) {
        int id = tid + s * 256;
        int r  = id >> 3;
        int cc = id & 7;
        CP_ASYNC16(sbu + (uint32_t)(bufoff + r * GSTRIDE + cc * 8) * 2u,
                   A + (size_t)(m0 + r) * K + k0 + cc * 8);
        CP_ASYNC16(sbu + (uint32_t)(bufoff + GOFF_W + r * GSTRIDE + cc * 8) * 2u,
                   W + (size_t)(n0 + r) * K + k0 + cc * 8);
    }
    CP_COMMIT();
}

__global__ __launch_bounds__(256, 2) void gemm_mma_kernel(
    const __half* __restrict__ A, const __half* __restrict__ W,
    const float* __restrict__ bias, float* __restrict__ C,
    __half* __restrict__ KV, __half* __restrict__ Q16,
    int M, int N, int K)
{
    extern __shared__ char smc[];
    const uint32_t sbu = smem_u32(smc);

    const int tid  = threadIdx.x;
    const int m0   = blockIdx.y << 7;
    const int n0   = blockIdx.x << 7;
    const int wid  = tid >> 5;
    const int lane = tid & 31;
    const int wm   = wid & 1;
    const int wn   = wid >> 1;

    const int qrow = lane >> 2;
    const int qk2  = (lane & 3) << 1;
    const int lml  = lane & 15;
    const int lmc  = (lane >> 4) << 3;

    float acc[4][4][4];
#pragma unroll
    for (int i = 0; i < 4; i++)
#pragma unroll
        for (int j = 0; j < 4; j++)
#pragma unroll
            for (int c = 0; c < 4; c++) acc[i][j][c] = 0.f;

    const int nchunks = K >> 6;

    gemm_issue_chunk(sbu, 0, A, W, m0, n0, K, 0, tid);

    for (int kc = 0; kc < nchunks; kc++) {
        const int buf = (kc & 1) ? GBUFH : 0;

        CP_WAIT0();
        __syncthreads();

        if (kc + 1 < nchunks)
            gemm_issue_chunk(sbu, (kc & 1) ? 0 : GBUFH, A, W, m0, n0, K,
                             (kc + 1) << 6, tid);

#pragma unroll
        for (int ks = 0; ks < 4; ks++) {
            const int co = ks * 16 + lmc;
            uint32_t a[4][4], b[2][4];
#pragma unroll
            for (int i = 0; i < 4; i++) {
                uint32_t ad = sbu +
                    (uint32_t)(buf + (wm * 64 + i * 16 + lml) * GSTRIDE + co) * 2u;
                LDM_X4(a[i][0], a[i][1], a[i][2], a[i][3], ad);
            }
#pragma unroll
            for (int jp = 0; jp < 2; jp++) {
                uint32_t ad = sbu +
                    (uint32_t)(buf + GOFF_W + (wn * 32 + jp * 16 + lml) * GSTRIDE + co) * 2u;
                LDM_X4(b[jp][0], b[jp][1], b[jp][2], b[jp][3], ad);
            }
#pragma unroll
            for (int i = 0; i < 4; i++)
#pragma unroll
                for (int jp = 0; jp < 2; jp++) {
                    mma_h(acc[i][2 * jp],     a[i][0], a[i][1], a[i][2], a[i][3],
                          b[jp][0], b[jp][2]);
                    mma_h(acc[i][2 * jp + 1], a[i][0], a[i][1], a[i][2], a[i][3],
                          b[jp][1], b[jp][3]);
                }
        }
    }

    // ---- epilogue
#pragma unroll
    for (int i = 0; i < 4; i++) {
        int gr = m0 + wm * 64 + i * 16 + qrow;
#pragma unroll
        for (int j = 0; j < 4; j++) {
            int gc = n0 + wn * 32 + j * 8 + qk2;
            float2 bv = *(const float2*)(bias + gc);
            float v00 = acc[i][j][0] + bv.x, v01 = acc[i][j][1] + bv.y;
            float v10 = acc[i][j][2] + bv.x, v11 = acc[i][j][3] + bv.y;
            if (Q16 == nullptr) {
                *(float2*)(C + (size_t)gr * N + gc)       = make_float2(v00, v01);
                *(float2*)(C + (size_t)(gr + 8) * N + gc) = make_float2(v10, v11);
            } else if (gc < 512) {
                *(uint32_t*)(Q16 + (size_t)gr * 512 + gc)       = h2pack(v00, v01);
                *(uint32_t*)(Q16 + (size_t)(gr + 8) * 512 + gc) = h2pack(v10, v11);
            } else {
                int isV  = gc >= 1024;
                int xx   = gc - (isV ? 1024 : 512);
                int head = xx >> 6, d = xx & 63;
                int off  = head * 128 + (isV ? 64 : 0) + d;
                *(uint32_t*)(KV + (size_t)gr * 1024 + off)       = h2pack(v00, v01);
                *(uint32_t*)(KV + (size_t)(gr + 8) * 1024 + off) = h2pack(v10, v11);
            }
        }
    }
}

// ===========================================================================
// Flash attention R17: 3 CTAs/SM, exp2 softmax, Q frags reloaded per tile,
// P packed to fp16 during softmax. 64-key j-tiles, cp.async double buffer.
// ===========================================================================
#define QOFF 0
#define BUFA 9216
#define BUFB 18432
#define BVOF 4608
#define ATT_SMEM_BYTES (27648 * 2)   // 55296

__device__ __forceinline__ void attn_cp_tile(
    uint32_t sbu, int bufoff, const __half* __restrict__ gkv,
    int rg, int h, int jt, int tid)
{
    const int tok = tid >> 2;
    const int c0  = tid & 3;
    const __half* srcb = gkv + (size_t)tok_index(rg, (jt << 6) + tok) * 1024 + h * 128;
#pragma unroll
    for (int s = 0; s < 4; s++) {
        int c = c0 + s * 4;
        int de = (c < 8) ? (bufoff + tok * 72 + c * 8)
                         : (bufoff + BVOF + tok * 72 + (c - 8) * 8);
        CP_ASYNC16(sbu + (uint32_t)de * 2u, (const char*)srcb + c * 16);
    }
}

__global__ __launch_bounds__(256, 3) void region_attn_mma_kernel(
    const float* __restrict__ epeg_w)
{
    extern __shared__ char smc[];
    __half* sb = (__half*)smc;
    const uint32_t sbu = smem_u32(smc);

    const int tid  = threadIdx.x;
    const int it   = blockIdx.x;
    const int h    = blockIdx.y;
    const int rg   = blockIdx.z;
    const int i0   = it << 7;

    const int warp = tid >> 5;
    const int lane = tid & 31;
    const int qr   = lane >> 2;
    const int q2   = (lane & 3) << 1;
    const int lml  = lane & 15;
    const int lmc  = (lane >> 4) << 3;

    const float w0 = epeg_w[h * 5 + 0];
    const float w1 = epeg_w[h * 5 + 1];
    const float w2 = epeg_w[h * 5 + 2];
    const float w3 = epeg_w[h * 5 + 3];
    const float w4 = epeg_w[h * 5 + 4];

    float* Qf = (float*)(smc + BUFA * 2);   // [132][68] fp32 staging
    for (int idx = tid; idx < 132 * 64; idx += 256) {
        int p = idx >> 6, d = idx & 63;
        int ii = i0 - 2 + p;
        float v = 0.f;
        if (ii >= 0 && ii < NREG)
            v = __half2float(g_q16[(size_t)tok_index(rg, ii) * DIMC + h * HD + d]);
        Qf[p * 68 + d] = v;
    }
    __syncthreads();

    // Q'' = SCALE*LOG2E*(q + conv5(q)) -> exp2-domain softmax
    for (int idx = tid; idx < 128 * 64; idx += 256) {
        int i = idx >> 6, d = idx & 63;
        const float* col = Qf + i * 68 + d;
        float v = col[2 * 68]
                + w0 * col[0] + w1 * col[68] + w2 * col[2 * 68]
                + w3 * col[3 * 68] + w4 * col[4 * 68];
        sb[QOFF + i * 72 + d] = __float2half(v * (SCALE_Q * LOG2E));
    }
    __syncthreads();

    attn_cp_tile(sbu, BUFA, g_kv, rg, h, 0, tid);
    CP_COMMIT();
    CP_WAIT0();
    __syncthreads();

    const uint32_t aqbase = sbu + (uint32_t)(QOFF + (warp * 16 + lml) * 72 + lmc) * 2u;

    float sO[8][4];
#pragma unroll
    for (int i = 0; i < 8; i++)
#pragma unroll
        for (int c = 0; c < 4; c++) sO[i][c] = 0.f;
    float mA = -1e30f, mB = -1e30f, lA = 0.f, lB = 0.f;

    for (int jt = 0; jt < 16; jt++) {
        const int buf = (jt & 1) ? BUFB : BUFA;
        if (jt + 1 < 16)
            attn_cp_tile(sbu, (jt & 1) ? BUFA : BUFB, g_kv, rg, h, jt + 1, tid);
        CP_COMMIT();

        // ---- S = Q'' @ K^T (Q frags reloaded per ks; warp: 16 x 64)
        float s[8][4];
#pragma unroll
        for (int nj = 0; nj < 8; nj++)
#pragma unroll
            for (int c = 0; c < 4; c++) s[nj][c] = 0.f;

#pragma unroll
        for (int ks = 0; ks < 4; ks++) {
            const int co = ks * 16;
            uint32_t q0_, q1_, q2_, q3_;
            LDM_X4(q0_, q1_, q2_, q3_, aqbase + (uint32_t)co * 2u);
#pragma unroll
            for (int njp = 0; njp < 4; njp++) {
                uint32_t k0_, k1_, k2_, k3_;
                uint32_t ad = sbu +
                    (uint32_t)(buf + (njp * 16 + lml) * 72 + co + lmc) * 2u;
                LDM_X4(k0_, k1_, k2_, k3_, ad);
                mma_h(s[2 * njp],     q0_, q1_, q2_, q3_, k0_, k2_);
                mma_h(s[2 * njp + 1], q0_, q1_, q2_, q3_, k1_, k3_);
            }
        }

        // ---- exp2 softmax; pack P to fp16 in the same pass
        float mtA = -1e30f, mtB = -1e30f;
#pragma unroll
        for (int nj = 0; nj < 8; nj++) {
            mtA = fmaxf(mtA, fmaxf(s[nj][0], s[nj][1]));
            mtB = fmaxf(mtB, fmaxf(s[nj][2], s[nj][3]));
        }
        mtA = fmaxf(mtA, __shfl_xor_sync(0xffffffffu, mtA, 1));
        mtA = fmaxf(mtA, __shfl_xor_sync(0xffffffffu, mtA, 2));
        mtB = fmaxf(mtB, __shfl_xor_sync(0xffffffffu, mtB, 1));
        mtB = fmaxf(mtB, __shfl_xor_sync(0xffffffffu, mtB, 2));
        float mnA = fmaxf(mA, mtA), mnB = fmaxf(mB, mtB);
        float alA = ex2f(mA - mnA), alB = ex2f(mB - mnB);
        mA = mnA; mB = mnB;

        uint32_t pk[4][4];
        float rsA = 0.f, rsB = 0.f;
#pragma unroll
        for (int kk = 0; kk < 4; kk++) {
            float e0 = ex2f(s[2 * kk][0] - mnA);
            float e1 = ex2f(s[2 * kk][1] - mnA);
            float e2 = ex2f(s[2 * kk][2] - mnB);
            float e3 = ex2f(s[2 * kk][3] - mnB);
            float f0 = ex2f(s[2 * kk + 1][0] - mnA);
            float f1 = ex2f(s[2 * kk + 1][1] - mnA);
            float f2 = ex2f(s[2 * kk + 1][2] - mnB);
            float f3 = ex2f(s[2 * kk + 1][3] - mnB);
            rsA += e0 + e1 + f0 + f1;
            rsB += e2 + e3 + f2 + f3;
            pk[kk][0] = h2pack(e0, e1);
            pk[kk][1] = h2pack(e2, e3);
            pk[kk][2] = h2pack(f0, f1);
            pk[kk][3] = h2pack(f2, f3);
        }
        rsA += __shfl_xor_sync(0xffffffffu, rsA, 1);
        rsA += __shfl_xor_sync(0xffffffffu, rsA, 2);
        rsB += __shfl_xor_sync(0xffffffffu, rsB, 1);
        rsB += __shfl_xor_sync(0xffffffffu, rsB, 2);
        lA = lA * alA + rsA;
        lB = lB * alB + rsB;

#pragma unroll
        for (int nd = 0; nd < 8; nd++) {
            sO[nd][0] *= alA; sO[nd][1] *= alA;
            sO[nd][2] *= alB; sO[nd][3] *= alB;
        }

        // ---- O += P @ V
#pragma unroll
        for (int kk = 0; kk < 4; kk++) {
            int vrow = kk * 16 + lml;
#pragma unroll
            for (int ndp = 0; ndp < 4; ndp++) {
                uint32_t v0_, v1_, v2_, v3_;
                uint32_t ad = sbu +
                    (uint32_t)(buf + BVOF + vrow * 72 + ndp * 16 + lmc) * 2u;
                LDM_X4_T(v0_, v1_, v2_, v3_, ad);
                mma_h(sO[2 * ndp],     pk[kk][0], pk[kk][1], pk[kk][2], pk[kk][3], v0_, v1_);
                mma_h(sO[2 * ndp + 1], pk[kk][0], pk[kk][1], pk[kk][2], pk[kk][3], v2_, v3_);
            }
        }

        CP_WAIT0();
        __syncthreads();
    }

    // ---- epilogue: O/l -> g_att (fp16, token order)
    float iA = 1.0f / lA, iB = 1.0f / lB;
    int rA = i0 + warp * 16 + qr;
    int tokA = tok_index(rg, rA);
    int tokB = tok_index(rg, rA + 8);
#pragma unroll
    for (int nd = 0; nd < 8; nd++) {
        int c = h * HD + nd * 8 + q2;
        *(uint32_t*)(g_att + (size_t)tokA * DIMC + c) =
            h2pack(sO[nd][0] * iA, sO[nd][1] * iA);
        *(uint32_t*)(g_att + (size_t)tokB * DIMC + c) =
            h2pack(sO[nd][2] * iB, sO[nd][3] * iB);
    }
}

// ---------------------------------------------------------------------------
extern "C" void kernel_launch(void* const* d_in, const int* in_sizes, int n_in,
                              void* d_out, int out_size) {
    const float* x      = (const float*)d_in[0];
    const float* qkv_w  = (const float*)d_in[1];
    const float* qkv_b  = (const float*)d_in[2];
    const float* proj_w = (const float*)d_in[3];
    const float* proj_b = (const float*)d_in[4];
    const float* epeg_w = (const float*)d_in[5];
    float* out = (float*)d_out;

    __half* q16     = nullptr;
    __half* kv_buf  = nullptr;
    __half* att_buf = nullptr;
    __half* x16     = nullptr;
    __half* w1      = nullptr;
    __half* w2      = nullptr;
    cudaGetSymbolAddress((void**)&q16,     g_q16);
    cudaGetSymbolAddress((void**)&kv_buf,  g_kv);
    cudaGetSymbolAddress((void**)&att_buf, g_att);
    cudaGetSymbolAddress((void**)&x16,     g_x16);
    cudaGetSymbolAddress((void**)&w1,      g_w1);
    cudaGetSymbolAddress((void**)&w2,      g_w2);

    cudaFuncSetAttribute(gemm_mma_kernel,
                         cudaFuncAttributeMaxDynamicSharedMemorySize,
                         GEMM_SMEM_BYTES);
    cudaFuncSetAttribute(region_attn_mma_kernel,
                         cudaFuncAttributeMaxDynamicSharedMemorySize,
                         ATT_SMEM_BYTES);

    // prepass: fp32 -> fp16
    cvt16_kernel<<<512, 256>>>(x,      x16, LTOK * DIMC / 4);
    cvt16_kernel<<<256, 256>>>(qkv_w,  w1,  QKVC * DIMC / 4);
    cvt16_kernel<<<128, 256>>>(proj_w, w2,  DIMC * DIMC / 4);

    // qkv = x @ qkv_w^T + qkv_b -> g_q16 (fp16) + g_kv (fp16)
    gemm_mma_kernel<<<dim3(QKVC / 128, LTOK / 128), 256, GEMM_SMEM_BYTES>>>(
        x16, w1, qkv_b, nullptr, kv_buf, q16, LTOK, QKVC, DIMC);

    // flash region attention (conv folded into Q'', exp2 softmax, 3 CTAs/SM)
    region_attn_mma_kernel<<<dim3(8, NH, 16), 256, ATT_SMEM_BYTES>>>(epeg_w);

    // out = att @ proj_w^T + proj_b
    gemm_mma_kernel<<<dim3(DIMC / 128, LTOK / 128), 256, GEMM_SMEM_BYTES>>>(
        att_buf, w2, proj_b, out, nullptr, nullptr, LTOK, DIMC, DIMC);
}